// round 2
// baseline (speedup 1.0000x reference)
#include <cuda_runtime.h>
#include <math.h>

// Problem constants: feature (4096,2048), centers (2048,2048)
#define D_K    2048
#define B_F    4096
#define C_C    2048
#define NUMR   2
#define NEARK  3
#define MAXIT  15
#define MARGINF 1.0f
#define IBIG   0x7FFFFFFF

// Device scratch
__device__ float g_Dfc[(size_t)B_F * C_C];   // 32 MB squared dists feature->centers
__device__ float g_Dcc[(size_t)C_C * C_C];   // 16 MB squared dists centers->centers
__device__ float g_fn[B_F];
__device__ float g_cn[C_C];
__device__ int4  g_near[C_C];                // packed 3-NN per center (w unused)
__device__ float g_hinge[B_F];

// ---------------------------------------------------------------------------
__global__ void row_norms_k(const float* __restrict__ A, int which) {
    const int row = blockIdx.x;
    const int tid = threadIdx.x;
    const float* a = A + (size_t)row * D_K;
    float s = 0.f;
    for (int i = tid; i < D_K; i += 256) {
        float v = a[i];
        s = fmaf(v, v, s);
    }
    __shared__ float red[256];
    red[tid] = s;
    __syncthreads();
    for (int st = 128; st > 0; st >>= 1) {
        if (tid < st) red[tid] += red[tid + st];
        __syncthreads();
    }
    if (tid == 0) {
        if (which == 0) g_fn[row] = red[0];
        else            g_cn[row] = red[0];
    }
}

// ---------------------------------------------------------------------------
// Tiled fp32 GEMM: D2[m][n] = a2[m] + b2[n] - 2 * (A_m . B_n)
// ---------------------------------------------------------------------------
#define BM 128
#define BN 128
#define BK 16

__global__ __launch_bounds__(256, 2)
void dist_gemm_k(const float* __restrict__ A, const float* __restrict__ Bm,
                 int M, int N, int mode) {
    __shared__ float As[BK][BM + 4];
    __shared__ float Bs[BK][BN + 4];

    const int tid = threadIdx.x;
    const int tx = tid & 15;
    const int ty = tid >> 4;
    const int bm = blockIdx.y * BM;
    const int bn = blockIdx.x * BN;

    const int lr = tid >> 2;
    const int lc = (tid & 3) << 2;

    const float* Aptr = A  + (size_t)(bm + lr) * D_K + lc;
    const float* Bptr = Bm + (size_t)(bn + lr) * D_K + lc;

    float acc[8][8];
#pragma unroll
    for (int i = 0; i < 8; i++)
#pragma unroll
        for (int j = 0; j < 8; j++) acc[i][j] = 0.f;

    for (int k0 = 0; k0 < D_K; k0 += BK) {
        float4 av0 = *(const float4*)(Aptr + k0);
        float4 av1 = *(const float4*)(Aptr + k0 + (size_t)64 * D_K);
        float4 bv0 = *(const float4*)(Bptr + k0);
        float4 bv1 = *(const float4*)(Bptr + k0 + (size_t)64 * D_K);

        __syncthreads();
        As[lc + 0][lr] = av0.x; As[lc + 1][lr] = av0.y;
        As[lc + 2][lr] = av0.z; As[lc + 3][lr] = av0.w;
        As[lc + 0][lr + 64] = av1.x; As[lc + 1][lr + 64] = av1.y;
        As[lc + 2][lr + 64] = av1.z; As[lc + 3][lr + 64] = av1.w;
        Bs[lc + 0][lr] = bv0.x; Bs[lc + 1][lr] = bv0.y;
        Bs[lc + 2][lr] = bv0.z; Bs[lc + 3][lr] = bv0.w;
        Bs[lc + 0][lr + 64] = bv1.x; Bs[lc + 1][lr + 64] = bv1.y;
        Bs[lc + 2][lr + 64] = bv1.z; Bs[lc + 3][lr + 64] = bv1.w;
        __syncthreads();

#pragma unroll
        for (int k = 0; k < BK; k++) {
            float ar[8], br[8];
            *(float4*)&ar[0] = *(const float4*)&As[k][ty * 8];
            *(float4*)&ar[4] = *(const float4*)&As[k][ty * 8 + 4];
            *(float4*)&br[0] = *(const float4*)&Bs[k][tx * 8];
            *(float4*)&br[4] = *(const float4*)&Bs[k][tx * 8 + 4];
#pragma unroll
            for (int i = 0; i < 8; i++)
#pragma unroll
                for (int j = 0; j < 8; j++)
                    acc[i][j] = fmaf(ar[i], br[j], acc[i][j]);
        }
    }

    float*       Dout = mode ? g_Dcc : g_Dfc;
    const float* a2   = mode ? g_cn  : g_fn;
    const float* b2   = g_cn;

#pragma unroll
    for (int i = 0; i < 8; i++) {
        const int m = bm + ty * 8 + i;
        const float am = a2[m];
        const int n0 = bn + tx * 8;
        float4 o0, o1;
        o0.x = fmaf(-2.f, acc[i][0], am + b2[n0 + 0]);
        o0.y = fmaf(-2.f, acc[i][1], am + b2[n0 + 1]);
        o0.z = fmaf(-2.f, acc[i][2], am + b2[n0 + 2]);
        o0.w = fmaf(-2.f, acc[i][3], am + b2[n0 + 3]);
        o1.x = fmaf(-2.f, acc[i][4], am + b2[n0 + 4]);
        o1.y = fmaf(-2.f, acc[i][5], am + b2[n0 + 5]);
        o1.z = fmaf(-2.f, acc[i][6], am + b2[n0 + 6]);
        o1.w = fmaf(-2.f, acc[i][7], am + b2[n0 + 7]);
        *(float4*)&Dout[(size_t)m * N + n0]     = o0;
        *(float4*)&Dout[(size_t)m * N + n0 + 4] = o1;
    }
}

// ---------------------------------------------------------------------------
// Per-center 3-NN: single pass, per-thread top-3 in registers, then merge.
// Lexicographic (val, idx) ordering = stable argsort semantics.
// ---------------------------------------------------------------------------
__global__ void near3_k() {
    const int c0  = blockIdx.x;
    const int tid = threadIdx.x;
    const float* row = g_Dcc + (size_t)c0 * C_C;

    float t0 = INFINITY, t1 = INFINITY, t2 = INFINITY;
    int   i0 = IBIG,     i1 = IBIG,     i2 = IBIG;

#pragma unroll
    for (int j = 0; j < C_C / 256; j++) {
        const int c = tid + j * 256;
        const float v = row[c];
        if (v < t2 || (v == t2 && c < i2)) {
            t2 = v; i2 = c;
            if (t2 < t1 || (t2 == t1 && i2 < i1)) {
                float tv = t1; int ti = i1; t1 = t2; i1 = i2; t2 = tv; i2 = ti;
                if (t1 < t0 || (t1 == t0 && i1 < i0)) {
                    tv = t0; ti = i0; t0 = t1; i0 = i1; t1 = tv; i1 = ti;
                }
            }
        }
    }

    __shared__ float sval[3 * 256];
    __shared__ int   sidx[3 * 256];
    sval[tid] = t0;       sidx[tid] = i0;
    sval[tid + 256] = t1; sidx[tid + 256] = i1;
    sval[tid + 512] = t2; sidx[tid + 512] = i2;
    __syncthreads();

    __shared__ float rv[256];
    __shared__ int   ri[256];
    __shared__ int   out3[3];

    for (int it = 0; it < NEARK; it++) {
        float bv = sval[tid]; int bi = sidx[tid];
#pragma unroll
        for (int k = 1; k < 3; k++) {
            float v = sval[tid + k * 256]; int ii = sidx[tid + k * 256];
            if (v < bv || (v == bv && ii < bi)) { bv = v; bi = ii; }
        }
        rv[tid] = bv; ri[tid] = bi;
        __syncthreads();
        for (int st = 128; st > 0; st >>= 1) {
            if (tid < st) {
                float v2 = rv[tid + st]; int i2b = ri[tid + st];
                if (v2 < rv[tid] || (v2 == rv[tid] && i2b < ri[tid])) {
                    rv[tid] = v2; ri[tid] = i2b;
                }
            }
            __syncthreads();
        }
        const float wv = rv[0];
        const int   wi = ri[0];
        if (tid == 0) out3[it] = wi;
        // remove winner (unique (val,idx) owner)
#pragma unroll
        for (int k = 0; k < 3; k++) {
            if (sval[tid + k * 256] == wv && sidx[tid + k * 256] == wi) {
                sval[tid + k * 256] = INFINITY;
                sidx[tid + k * 256] = IBIG;
            }
        }
        __syncthreads();
    }

    if (tid == 0) {
        int4 p; p.x = out3[0]; p.y = out3[1]; p.z = out3[2]; p.w = 0;
        g_near[c0] = p;
    }
}

// ---------------------------------------------------------------------------
// Per-feature-row selection, non-iterative:
//   T = lex-min (D, c) over trusted c  (trusted: c!=l and l not in near[c])
//   rank(T) = #{c!=l : (D,c) <lex (Tval,Tidx)}; found iff rank <= 14
// ---------------------------------------------------------------------------
__global__ void select_k() {
    const int b   = blockIdx.x;
    const int l   = b / NUMR;
    const int tid = threadIdx.x;
    const float* row = g_Dfc + (size_t)b * C_C;

    float v[C_C / 256];
    float bv = INFINITY; int bi = IBIG;

#pragma unroll
    for (int j = 0; j < C_C / 256; j++) {
        const int c = tid + j * 256;
        const float d = row[c];
        v[j] = d;
        const int4 nr = g_near[c];
        const bool tr = (c != l) && (nr.x != l) && (nr.y != l) && (nr.z != l);
        if (tr && (d < bv || (d == bv && c < bi))) { bv = d; bi = c; }
    }

    __shared__ float rv[256];
    __shared__ int   ri[256];
    rv[tid] = bv; ri[tid] = bi;
    __syncthreads();
    for (int st = 128; st > 0; st >>= 1) {
        if (tid < st) {
            float v2 = rv[tid + st]; int i2 = ri[tid + st];
            if (v2 < rv[tid] || (v2 == rv[tid] && i2 < ri[tid])) {
                rv[tid] = v2; ri[tid] = i2;
            }
        }
        __syncthreads();
    }
    const float Tval = rv[0];
    const int   Tidx = ri[0];
    __syncthreads();

    int cnt = 0;
#pragma unroll
    for (int j = 0; j < C_C / 256; j++) {
        const int c = tid + j * 256;
        if (c != l && (v[j] < Tval || (v[j] == Tval && c < Tidx))) cnt++;
    }
    __shared__ int rc[256];
    rc[tid] = cnt;
    __syncthreads();
    for (int st = 128; st > 0; st >>= 1) {
        if (tid < st) rc[tid] += rc[tid + st];
        __syncthreads();
    }

    if (tid == 0) {
        const bool found = (Tidx < C_C) && (rc[0] <= MAXIT - 1);
        const float same = sqrtf(fmaxf(row[l], 0.f));
        const float md   = found ? sqrtf(fmaxf(Tval, 0.f)) : 0.f;
        g_hinge[b] = fmaxf(MARGINF + same - md, 0.f);
    }
}

// ---------------------------------------------------------------------------
__global__ void reduce_k(float* __restrict__ out) {
    const int tid = threadIdx.x;
    __shared__ float red[256];
    float s = 0.f;
    for (int i = tid; i < B_F; i += 256) s += g_hinge[i];
    red[tid] = s;
    __syncthreads();
    for (int st = 128; st > 0; st >>= 1) {
        if (tid < st) red[tid] += red[tid + st];
        __syncthreads();
    }
    if (tid == 0) out[0] = red[0] * (1.0f / (float)B_F);
}

// ---------------------------------------------------------------------------
extern "C" void kernel_launch(void* const* d_in, const int* in_sizes, int n_in,
                              void* d_out, int out_size) {
    (void)in_sizes; (void)n_in; (void)out_size;
    const float* feat = (const float*)d_in[0];
    const float* cent = (const float*)d_in[1];
    float* out = (float*)d_out;

    row_norms_k<<<B_F, 256>>>(feat, 0);
    row_norms_k<<<C_C, 256>>>(cent, 1);

    dim3 gcc(C_C / BN, C_C / BM);
    dim3 gfc(C_C / BN, B_F / BM);
    dist_gemm_k<<<gcc, 256>>>(cent, cent, C_C, C_C, 1);
    dist_gemm_k<<<gfc, 256>>>(feat, cent, B_F, C_C, 0);

    near3_k<<<C_C, 256>>>();
    select_k<<<B_F, 256>>>();
    reduce_k<<<1, 256>>>(out);
}

// round 5
// speedup vs baseline: 2.3413x; 2.3413x over previous
#include <cuda_runtime.h>
#include <cuda_bf16.h>
#include <math.h>
#include <stdint.h>

#define D_K    2048
#define B_F    4096
#define C_C    2048
#define NUMR   2
#define NEARK  3
#define MAXIT  15
#define MARGINF 1.0f
#define IBIG   0x7FFFFFFF

// ---------------------------------------------------------------------------
// Device scratch
// ---------------------------------------------------------------------------
__device__ float g_Dfc[(size_t)B_F * C_C];   // 32 MB
__device__ float g_Dcc[(size_t)C_C * C_C];   // 16 MB
__device__ float g_fn[B_F];
__device__ float g_cn[C_C];
__device__ int4  g_near[C_C];
__device__ float g_hinge[B_F];
__device__ __nv_bfloat16 g_fh[(size_t)B_F * D_K];
__device__ __nv_bfloat16 g_fl[(size_t)B_F * D_K];
__device__ __nv_bfloat16 g_ch[(size_t)C_C * D_K];
__device__ __nv_bfloat16 g_cl[(size_t)C_C * D_K];

// ---------------------------------------------------------------------------
// Baseline-PTX helpers (sm_80+ features only; no 'a'-target instructions)
// ---------------------------------------------------------------------------
__device__ __forceinline__ uint32_t smem_u32(const void* p) {
    uint32_t a;
    asm("{ .reg .u64 t; cvta.to.shared.u64 t, %1; cvt.u32.u64 %0, t; }" : "=r"(a) : "l"(p));
    return a;
}
__device__ __forceinline__ void cp16(uint32_t s, const void* g) {
    asm volatile("cp.async.cg.shared.global [%0], [%1], 16;" :: "r"(s), "l"(g));
}
#define CP_COMMIT() asm volatile("cp.async.commit_group;" ::: "memory")
#define CP_WAIT1()  asm volatile("cp.async.wait_group 1;" ::: "memory")
#define CP_WAIT0()  asm volatile("cp.async.wait_group 0;" ::: "memory")

__device__ __forceinline__ void ldsm4(uint32_t& r0, uint32_t& r1, uint32_t& r2, uint32_t& r3,
                                      uint32_t addr) {
    asm volatile("ldmatrix.sync.aligned.m8n8.x4.shared.b16 {%0,%1,%2,%3}, [%4];"
                 : "=r"(r0), "=r"(r1), "=r"(r2), "=r"(r3) : "r"(addr));
}
__device__ __forceinline__ void mma16816(float c[4], const uint32_t a[4],
                                         uint32_t b0, uint32_t b1) {
    asm volatile("mma.sync.aligned.m16n8k16.row.col.f32.bf16.bf16.f32 "
                 "{%0,%1,%2,%3}, {%4,%5,%6,%7}, {%8,%9}, {%0,%1,%2,%3};"
                 : "+f"(c[0]), "+f"(c[1]), "+f"(c[2]), "+f"(c[3])
                 : "r"(a[0]), "r"(a[1]), "r"(a[2]), "r"(a[3]), "r"(b0), "r"(b1));
}

// ---------------------------------------------------------------------------
// fp32 -> bf16 hi/lo split
// ---------------------------------------------------------------------------
__global__ void split_k(const float* __restrict__ A,
                        __nv_bfloat16* __restrict__ hi,
                        __nv_bfloat16* __restrict__ lo, int n4) {
    const int i = blockIdx.x * blockDim.x + threadIdx.x;
    if (i >= n4) return;
    float4 v = ((const float4*)A)[i];
    __nv_bfloat16 h0 = __float2bfloat16(v.x);
    __nv_bfloat16 h1 = __float2bfloat16(v.y);
    __nv_bfloat16 h2 = __float2bfloat16(v.z);
    __nv_bfloat16 h3 = __float2bfloat16(v.w);
    __nv_bfloat16 l0 = __float2bfloat16(v.x - __bfloat162float(h0));
    __nv_bfloat16 l1 = __float2bfloat16(v.y - __bfloat162float(h1));
    __nv_bfloat16 l2 = __float2bfloat16(v.z - __bfloat162float(h2));
    __nv_bfloat16 l3 = __float2bfloat16(v.w - __bfloat162float(h3));
    __nv_bfloat162* H = (__nv_bfloat162*)hi;
    __nv_bfloat162* L = (__nv_bfloat162*)lo;
    H[i * 2 + 0] = __nv_bfloat162(h0, h1);
    H[i * 2 + 1] = __nv_bfloat162(h2, h3);
    L[i * 2 + 0] = __nv_bfloat162(l0, l1);
    L[i * 2 + 1] = __nv_bfloat162(l2, l3);
}

// ---------------------------------------------------------------------------
__global__ void row_norms_k(const float* __restrict__ A, int which) {
    const int row = blockIdx.x;
    const int tid = threadIdx.x;
    const float* a = A + (size_t)row * D_K;
    float s = 0.f;
    for (int i = tid; i < D_K; i += 256) { float v = a[i]; s = fmaf(v, v, s); }
    __shared__ float red[256];
    red[tid] = s; __syncthreads();
    for (int st = 128; st > 0; st >>= 1) { if (tid < st) red[tid] += red[tid + st]; __syncthreads(); }
    if (tid == 0) { if (which == 0) g_fn[row] = red[0]; else g_cn[row] = red[0]; }
}

// ---------------------------------------------------------------------------
// Tensor-core distance GEMM via warp-level mma.sync (bf16 hi/lo, fp32 accum):
//   Dout[m][n] = a2[m] + b2[n] - 2 * (Ah+Al)_m . (Bh+Bl)_n   (3 terms)
// CTA tile 128x128, K-chunk 32, 2-stage cp.async double buffer.
// ---------------------------------------------------------------------------
#define KC    32
#define NIT   (D_K / KC)            // 64
#define PADW  40                    // smem row stride (bf16 elems) -> 80 B
#define TILEB (128 * PADW * 2)      // 10240 B per tile
#define STAGEB (4 * TILEB)          // Ah, Al, Bh, Bl
#define SMEMB  (2 * STAGEB)         // 81920 B

__global__ void __launch_bounds__(256)
mma_gemm_k(const __nv_bfloat16* __restrict__ Ah, const __nv_bfloat16* __restrict__ Al,
           const __nv_bfloat16* __restrict__ Bh, const __nv_bfloat16* __restrict__ Bl,
           float* __restrict__ Dout, const float* __restrict__ a2,
           const float* __restrict__ b2, int Ncols) {
    extern __shared__ char smem[];
    const uint32_t sb = smem_u32(smem);

    const int tid  = threadIdx.x;
    const int lane = tid & 31;
    const int wid  = tid >> 5;
    const int wm   = wid & 1;        // 2 m-tiles of 64
    const int wn   = wid >> 1;       // 4 n-tiles of 32
    const int bm   = blockIdx.y * 128;
    const int bn   = blockIdx.x * 128;

    const __nv_bfloat16* gbase[4] = {
        Ah + (size_t)bm * D_K, Al + (size_t)bm * D_K,
        Bh + (size_t)bn * D_K, Bl + (size_t)bn * D_K };

    // per-thread load mapping: 2048 16B-chunks/stage, 8 per thread, tile = q/2
    const int rem0 = tid;            // q even: rem = tid; q odd: rem = 256+tid
    // ldmatrix per-lane base offsets (bytes within a tile)
    // A (x4): lanes 0-7 rows 0-7 ch0 | 8-15 rows 8-15 ch0 | 16-23 rows 0-7 ch1 | 24-31 rows 8-15 ch1
    const int a_row = (lane & 15);
    const int a_ch  = lane >> 4;
    const uint32_t aoff = (uint32_t)((wm * 64 + a_row) * (PADW * 2) + a_ch * 16);
    // B (x4): mats: (n0-7,ch0)(n0-7,ch1)(n8-15,ch0)(n8-15,ch1)
    const int b_row = (lane & 7) + ((lane >> 4) << 3);
    const int b_ch  = (lane >> 3) & 1;
    const uint32_t boff = (uint32_t)((wn * 32 + b_row) * (PADW * 2) + b_ch * 16);

    float acc[4][4][4];
#pragma unroll
    for (int i = 0; i < 4; i++)
#pragma unroll
        for (int j = 0; j < 4; j++)
#pragma unroll
            for (int q = 0; q < 4; q++) acc[i][j][q] = 0.f;

    // ---- stage loader ----
    auto load_stage = [&](int buf, int kc) {
        const int koff = kc * KC;
        const uint32_t sbase = sb + buf * STAGEB;
#pragma unroll
        for (int q = 0; q < 8; q++) {
            const int t   = q >> 1;
            const int rem = ((q & 1) << 8) + rem0;
            const int row = rem >> 2;
            const int ch  = rem & 3;
            cp16(sbase + t * TILEB + row * (PADW * 2) + ch * 16,
                 gbase[t] + (size_t)row * D_K + koff + ch * 8);
        }
        CP_COMMIT();
    };

    load_stage(0, 0);

    for (int kc = 0; kc < NIT; kc++) {
        if (kc + 1 < NIT) load_stage((kc + 1) & 1, kc + 1);
        if (kc + 1 < NIT) CP_WAIT1(); else CP_WAIT0();
        __syncthreads();

        const uint32_t st = sb + (kc & 1) * STAGEB;
#pragma unroll
        for (int ks = 0; ks < 2; ks++) {
            uint32_t ah[4][4], al[4][4], bh[2][4], bl[2][4];
#pragma unroll
            for (int mf = 0; mf < 4; mf++) {
                const uint32_t ao = aoff + mf * 16 * (PADW * 2) + ks * 32;
                ldsm4(ah[mf][0], ah[mf][1], ah[mf][2], ah[mf][3], st + 0 * TILEB + ao);
                ldsm4(al[mf][0], al[mf][1], al[mf][2], al[mf][3], st + 1 * TILEB + ao);
            }
#pragma unroll
            for (int nf2 = 0; nf2 < 2; nf2++) {
                const uint32_t bo = boff + nf2 * 16 * (PADW * 2) + ks * 32;
                ldsm4(bh[nf2][0], bh[nf2][1], bh[nf2][2], bh[nf2][3], st + 2 * TILEB + bo);
                ldsm4(bl[nf2][0], bl[nf2][1], bl[nf2][2], bl[nf2][3], st + 3 * TILEB + bo);
            }
#pragma unroll
            for (int mf = 0; mf < 4; mf++) {
#pragma unroll
                for (int nf = 0; nf < 4; nf++) {
                    const int h = nf >> 1, o = (nf & 1) << 1;
                    mma16816(acc[mf][nf], ah[mf], bh[h][o], bh[h][o + 1]);  // hi*hi
                    mma16816(acc[mf][nf], ah[mf], bl[h][o], bl[h][o + 1]);  // hi*lo
                    mma16816(acc[mf][nf], al[mf], bh[h][o], bh[h][o + 1]);  // lo*hi
                }
            }
        }
        __syncthreads();
    }

    // ---- epilogue: d2 = a2[m] + b2[n] - 2*dot ----
#pragma unroll
    for (int mf = 0; mf < 4; mf++) {
        const int r0  = bm + wm * 64 + mf * 16 + (lane >> 2);
        const float am0 = a2[r0];
        const float am1 = a2[r0 + 8];
        float* out0 = Dout + (size_t)r0 * Ncols;
        float* out1 = Dout + (size_t)(r0 + 8) * Ncols;
#pragma unroll
        for (int nf = 0; nf < 4; nf++) {
            const int n = bn + wn * 32 + nf * 8 + ((lane & 3) << 1);
            const float b0 = b2[n], b1 = b2[n + 1];
            float2 p0, p1;
            p0.x = fmaf(-2.f, acc[mf][nf][0], am0 + b0);
            p0.y = fmaf(-2.f, acc[mf][nf][1], am0 + b1);
            p1.x = fmaf(-2.f, acc[mf][nf][2], am1 + b0);
            p1.y = fmaf(-2.f, acc[mf][nf][3], am1 + b1);
            *(float2*)(out0 + n) = p0;
            *(float2*)(out1 + n) = p1;
        }
    }
}

// ---------------------------------------------------------------------------
// Per-center 3-NN (single pass + merge)
// ---------------------------------------------------------------------------
__global__ void near3_k() {
    const int c0  = blockIdx.x;
    const int tid = threadIdx.x;
    const float* row = g_Dcc + (size_t)c0 * C_C;

    float t0 = INFINITY, t1 = INFINITY, t2 = INFINITY;
    int   i0 = IBIG,     i1 = IBIG,     i2 = IBIG;
#pragma unroll
    for (int j = 0; j < C_C / 256; j++) {
        const int c = tid + j * 256;
        const float v = row[c];
        if (v < t2 || (v == t2 && c < i2)) {
            t2 = v; i2 = c;
            if (t2 < t1 || (t2 == t1 && i2 < i1)) {
                float tv = t1; int ti = i1; t1 = t2; i1 = i2; t2 = tv; i2 = ti;
                if (t1 < t0 || (t1 == t0 && i1 < i0)) {
                    tv = t0; ti = i0; t0 = t1; i0 = i1; t1 = tv; i1 = ti;
                }
            }
        }
    }
    __shared__ float sval[3 * 256];
    __shared__ int   sidx[3 * 256];
    sval[tid] = t0;       sidx[tid] = i0;
    sval[tid + 256] = t1; sidx[tid + 256] = i1;
    sval[tid + 512] = t2; sidx[tid + 512] = i2;
    __syncthreads();

    __shared__ float rv[256];
    __shared__ int   ri[256];
    __shared__ int   out3[3];
    for (int it = 0; it < NEARK; it++) {
        float bv = sval[tid]; int bi = sidx[tid];
#pragma unroll
        for (int k = 1; k < 3; k++) {
            float v = sval[tid + k * 256]; int ii = sidx[tid + k * 256];
            if (v < bv || (v == bv && ii < bi)) { bv = v; bi = ii; }
        }
        rv[tid] = bv; ri[tid] = bi;
        __syncthreads();
        for (int st = 128; st > 0; st >>= 1) {
            if (tid < st) {
                float v2 = rv[tid + st]; int j2 = ri[tid + st];
                if (v2 < rv[tid] || (v2 == rv[tid] && j2 < ri[tid])) { rv[tid] = v2; ri[tid] = j2; }
            }
            __syncthreads();
        }
        const float wv = rv[0]; const int wi = ri[0];
        if (tid == 0) out3[it] = wi;
#pragma unroll
        for (int k = 0; k < 3; k++) {
            if (sval[tid + k * 256] == wv && sidx[tid + k * 256] == wi) {
                sval[tid + k * 256] = INFINITY; sidx[tid + k * 256] = IBIG;
            }
        }
        __syncthreads();
    }
    if (tid == 0) { int4 p; p.x = out3[0]; p.y = out3[1]; p.z = out3[2]; p.w = 0; g_near[c0] = p; }
}

// ---------------------------------------------------------------------------
// Per-feature-row selection (non-iterative)
// ---------------------------------------------------------------------------
__global__ void select_k() {
    const int b   = blockIdx.x;
    const int l   = b / NUMR;
    const int tid = threadIdx.x;
    const float* row = g_Dfc + (size_t)b * C_C;

    float v[C_C / 256];
    float bv = INFINITY; int bi = IBIG;
#pragma unroll
    for (int j = 0; j < C_C / 256; j++) {
        const int c = tid + j * 256;
        const float d = row[c];
        v[j] = d;
        const int4 nr = g_near[c];
        const bool tr = (c != l) && (nr.x != l) && (nr.y != l) && (nr.z != l);
        if (tr && (d < bv || (d == bv && c < bi))) { bv = d; bi = c; }
    }
    __shared__ float rv[256];
    __shared__ int   ri[256];
    rv[tid] = bv; ri[tid] = bi;
    __syncthreads();
    for (int st = 128; st > 0; st >>= 1) {
        if (tid < st) {
            float v2 = rv[tid + st]; int i2 = ri[tid + st];
            if (v2 < rv[tid] || (v2 == rv[tid] && i2 < ri[tid])) { rv[tid] = v2; ri[tid] = i2; }
        }
        __syncthreads();
    }
    const float Tval = rv[0]; const int Tidx = ri[0];
    __syncthreads();

    int cnt = 0;
#pragma unroll
    for (int j = 0; j < C_C / 256; j++) {
        const int c = tid + j * 256;
        if (c != l && (v[j] < Tval || (v[j] == Tval && c < Tidx))) cnt++;
    }
    __shared__ int rc[256];
    rc[tid] = cnt;
    __syncthreads();
    for (int st = 128; st > 0; st >>= 1) { if (tid < st) rc[tid] += rc[tid + st]; __syncthreads(); }

    if (tid == 0) {
        const bool found = (Tidx < C_C) && (rc[0] <= MAXIT - 1);
        const float same = sqrtf(fmaxf(row[l], 0.f));
        const float md   = found ? sqrtf(fmaxf(Tval, 0.f)) : 0.f;
        g_hinge[b] = fmaxf(MARGINF + same - md, 0.f);
    }
}

// ---------------------------------------------------------------------------
__global__ void reduce_k(float* __restrict__ out) {
    const int tid = threadIdx.x;
    __shared__ float red[256];
    float s = 0.f;
    for (int i = tid; i < B_F; i += 256) s += g_hinge[i];
    red[tid] = s;
    __syncthreads();
    for (int st = 128; st > 0; st >>= 1) { if (tid < st) red[tid] += red[tid + st]; __syncthreads(); }
    if (tid == 0) out[0] = red[0] * (1.0f / (float)B_F);
}

// ---------------------------------------------------------------------------
extern "C" void kernel_launch(void* const* d_in, const int* in_sizes, int n_in,
                              void* d_out, int out_size) {
    (void)in_sizes; (void)n_in; (void)out_size;
    const float* feat = (const float*)d_in[0];
    const float* cent = (const float*)d_in[1];
    float* out = (float*)d_out;

    cudaFuncSetAttribute(mma_gemm_k, cudaFuncAttributeMaxDynamicSharedMemorySize, SMEMB);

    __nv_bfloat16 *fh, *fl, *ch, *cl;
    float *dfc, *dcc, *fn, *cn;
    cudaGetSymbolAddress((void**)&fh, g_fh);
    cudaGetSymbolAddress((void**)&fl, g_fl);
    cudaGetSymbolAddress((void**)&ch, g_ch);
    cudaGetSymbolAddress((void**)&cl, g_cl);
    cudaGetSymbolAddress((void**)&dfc, g_Dfc);
    cudaGetSymbolAddress((void**)&dcc, g_Dcc);
    cudaGetSymbolAddress((void**)&fn, g_fn);
    cudaGetSymbolAddress((void**)&cn, g_cn);

    split_k<<<(B_F * D_K / 4 + 255) / 256, 256>>>(feat, fh, fl, B_F * D_K / 4);
    split_k<<<(C_C * D_K / 4 + 255) / 256, 256>>>(cent, ch, cl, C_C * D_K / 4);
    row_norms_k<<<B_F, 256>>>(feat, 0);
    row_norms_k<<<C_C, 256>>>(cent, 1);

    dim3 gcc(C_C / 128, C_C / 128);   // 16 x 16
    dim3 gfc(C_C / 128, B_F / 128);   // 16 x 32
    mma_gemm_k<<<gcc, 256, SMEMB>>>(ch, cl, ch, cl, dcc, cn, cn, C_C);
    mma_gemm_k<<<gfc, 256, SMEMB>>>(fh, fl, ch, cl, dfc, fn, cn, C_C);

    near3_k<<<C_C, 256>>>();
    select_k<<<B_F, 256>>>();
    reduce_k<<<1, 256>>>(out);
}